// round 6
// baseline (speedup 1.0000x reference)
#include <cuda_runtime.h>
#include <cuda_fp16.h>
#include <cstdint>
#include <cstddef>

#define B_ 4
#define S_ 2048
#define E_ 1024
#define H_ 16
#define D_ 64
#define LOG2E 1.4426950408889634f

// Scratch (allocation-guard-legal): fp16-converted operands + attention output.
__device__ __half g_qh[B_ * S_ * E_];
__device__ __half g_kh[B_ * S_ * E_];
__device__ __half g_vh[B_ * S_ * E_];
__device__ __half g_wh[E_ * E_];
__device__ __half g_attn[B_ * S_ * E_];   // attn output (fp16)

__device__ __forceinline__ float ex2f(float x) {
    float y;
    asm("ex2.approx.ftz.f32 %0, %1;" : "=f"(y) : "f"(x));
    return y;
}
__device__ __forceinline__ unsigned packh2(float lo, float hi) {
    __half2 h = __floats2half2_rn(lo, hi);
    return *reinterpret_cast<unsigned*>(&h);
}
// pack two f32 into f16x2 (lo in low half), then exp2 both halves on MUFU.
__device__ __forceinline__ unsigned cvth2(float hi, float lo) {
    unsigned r;
    asm("cvt.rn.f16x2.f32 %0, %1, %2;" : "=r"(r) : "f"(hi), "f"(lo));
    return r;
}
__device__ __forceinline__ unsigned h2ex2(unsigned x) {
    unsigned y;
    asm("ex2.approx.f16x2 %0, %1;" : "=r"(y) : "r"(x));
    return y;
}
__device__ __forceinline__ void mma_f16(float* d, const unsigned* a, unsigned b0, unsigned b1) {
    asm volatile(
        "mma.sync.aligned.m16n8k16.row.col.f32.f16.f16.f32 "
        "{%0,%1,%2,%3}, {%4,%5,%6,%7}, {%8,%9}, {%0,%1,%2,%3};\n"
        : "+f"(d[0]), "+f"(d[1]), "+f"(d[2]), "+f"(d[3])
        : "r"(a[0]), "r"(a[1]), "r"(a[2]), "r"(a[3]), "r"(b0), "r"(b1));
}
__device__ __forceinline__ void ldm4(unsigned* r, unsigned addr) {
    asm volatile("ldmatrix.sync.aligned.m8n8.x4.shared.b16 {%0,%1,%2,%3}, [%4];"
        : "=r"(r[0]), "=r"(r[1]), "=r"(r[2]), "=r"(r[3]) : "r"(addr));
}
__device__ __forceinline__ void ldm4t(unsigned* r, unsigned addr) {
    asm volatile("ldmatrix.sync.aligned.m8n8.x4.trans.shared.b16 {%0,%1,%2,%3}, [%4];"
        : "=r"(r[0]), "=r"(r[1]), "=r"(r[2]), "=r"(r[3]) : "r"(addr));
}
__device__ __forceinline__ unsigned stou(const void* p) {
    unsigned a;
    asm("{ .reg .u64 tmp; cvta.to.shared.u64 tmp, %1; cvt.u32.u64 %0, tmp; }"
        : "=r"(a) : "l"(p));
    return a;
}
__device__ __forceinline__ void cp16(unsigned dst, const void* src) {
    asm volatile("cp.async.cg.shared.global [%0], [%1], 16;" :: "r"(dst), "l"(src));
}
__device__ __forceinline__ void cp_commit() { asm volatile("cp.async.commit_group;"); }
template <int N> __device__ __forceinline__ void cp_wait() {
    asm volatile("cp.async.wait_group %0;" :: "n"(N));
}

// XOR-swizzled 16B-unit offset within a tile whose rows are 64 halves (128B).
__device__ __forceinline__ unsigned swz(int r, int cb) {
    return (unsigned)(r * 8 + (cb ^ (r & 7)));
}

// ---------------------------------------------------------------------------
// Fused fp32 -> fp16 convert for q (scaled), k, v, w in ONE launch.
// ---------------------------------------------------------------------------
#define NQ4 (B_ * S_ * E_ / 4)
#define NW4 (E_ * E_ / 4)

__global__ void __launch_bounds__(256)
cvt_all_kernel(const float* __restrict__ q, const float* __restrict__ k,
               const float* __restrict__ v, const float* __restrict__ w) {
    int i = blockIdx.x * blockDim.x + threadIdx.x;
    const float* src;
    __half* dst;
    float scale = 1.0f;
    int j = i;
    if (j < NQ4)                { src = q; dst = g_qh; scale = 0.125f * LOG2E; }
    else if ((j -= NQ4) < NQ4)  { src = k; dst = g_kh; }
    else if ((j -= NQ4) < NQ4)  { src = v; dst = g_vh; }
    else {
        j -= NQ4;
        if (j >= NW4) return;
        src = w; dst = g_wh;
    }
    float4 f = ((const float4*)src)[j];
    uint2 u;
    u.x = packh2(f.x * scale, f.y * scale);
    u.y = packh2(f.z * scale, f.w * scale);
    ((uint2*)dst)[j] = u;
}

// ---------------------------------------------------------------------------
// Flash attention, fp16 mma m16n8k16. CTA = (b,h,128 q-rows), 4 warps of
// 32 q-rows, BN=64. 4-stage cp.async KV ring (one barrier per tile);
// P stays in registers; half2 exponentials feed PV fragments directly.
// ---------------------------------------------------------------------------
#define QTILE_B (128 * 128)        // 16384 B
#define KVTILE_B (64 * 128)        // 8192 B per K or V tile
#define KVSTAGE_B (2 * KVTILE_B)   // K+V per stage
#define NSTAGE 4
#define NKT (S_ / 64)

__global__ void __launch_bounds__(128, 2)
attn_kernel() {
    extern __shared__ __align__(16) unsigned char smraw[];
    const unsigned sb  = stou(smraw);
    const unsigned Qb  = sb;
    const unsigned KVb = sb + QTILE_B;

    const int tid = threadIdx.x, wid = tid >> 5, lane = tid & 31;
    const int g = lane >> 2, t = lane & 3;
    const int qblk = blockIdx.x;
    const int h = blockIdx.y & (H_ - 1);
    const int b = blockIdx.y >> 4;

    const size_t qbase  = ((size_t)(b * S_ + qblk * 128)) * E_ + h * D_;
    const size_t kvbase = ((size_t)(b * S_)) * E_ + h * D_;

    // Q tile load (group 0)
    {
        const __half* qp = g_qh + qbase;
        #pragma unroll
        for (int n = 0; n < 8; ++n) {
            int c = tid + 128 * n;
            int r = c >> 3, cb = c & 7;
            cp16(Qb + swz(r, cb) * 16, qp + (size_t)r * E_ + cb * 8);
        }
        cp_commit();
    }

    auto load_kv = [&](int kt, int buf) {
        const __half* kp = g_kh + kvbase + (size_t)(kt * 64) * E_;
        const __half* vp = g_vh + kvbase + (size_t)(kt * 64) * E_;
        unsigned kd = KVb + buf * KVSTAGE_B;
        unsigned vd = kd + KVTILE_B;
        #pragma unroll
        for (int n = 0; n < 4; ++n) {
            int c = tid + 128 * n;
            int r = c >> 3, cb = c & 7;
            cp16(kd + swz(r, cb) * 16, kp + (size_t)r * E_ + cb * 8);
            cp16(vd + swz(r, cb) * 16, vp + (size_t)r * E_ + cb * 8);
        }
    };
    load_kv(0, 0); cp_commit();   // group 1
    load_kv(1, 1); cp_commit();   // group 2

    // Q fragments (groups pending: kv0,kv1 -> wait<2> completes Q group)
    cp_wait<2>();
    __syncthreads();
    unsigned qa[2][4][4];
    const int qr = 32 * wid;
    {
        int rA = lane & 15, cA = lane >> 4;
        #pragma unroll
        for (int mt = 0; mt < 2; ++mt)
            #pragma unroll
            for (int kk = 0; kk < 4; ++kk)
                ldm4(qa[mt][kk], Qb + swz(qr + 16 * mt + rA, 2 * kk + cA) * 16);
    }

    float oacc[2][8][4] = {};
    float m[2][2] = {{-1e30f, -1e30f}, {-1e30f, -1e30f}};
    float l[2][2] = {{0.f, 0.f}, {0.f, 0.f}};

    const int rK = ((lane & 16) >> 1) + (lane & 7);
    const int cK = (lane >> 3) & 1;
    const int rV = lane & 15;
    const int cV = lane >> 4;

    for (int kt = 0; kt < NKT; ++kt) {
        // Prefetch distance 2 into a 4-deep ring: the buffer a pre-barrier
        // cp.async targets was last read 2 iterations ago -> one barrier/iter
        // is enough (warps can only skew by < 2 iterations across one barrier).
        if (kt + 2 < NKT) { load_kv(kt + 2, (kt + 2) & 3); cp_commit(); cp_wait<2>(); }
        else if (kt + 1 < NKT) { cp_wait<1>(); }
        else { cp_wait<0>(); }
        __syncthreads();

        const unsigned Kb = KVb + (kt & 3) * KVSTAGE_B;
        const unsigned Vb = Kb + KVTILE_B;

        // ---- S = Q K^T : 32x64 per warp ----
        float sacc[2][8][4] = {};
        #pragma unroll
        for (int jp = 0; jp < 4; ++jp) {
            unsigned kb[4][4];
            #pragma unroll
            for (int kk = 0; kk < 4; ++kk)
                ldm4(kb[kk], Kb + swz(16 * jp + rK, 2 * kk + cK) * 16);
            #pragma unroll
            for (int kk = 0; kk < 4; ++kk) {
                mma_f16(sacc[0][2 * jp],     qa[0][kk], kb[kk][0], kb[kk][1]);
                mma_f16(sacc[1][2 * jp],     qa[1][kk], kb[kk][0], kb[kk][1]);
                mma_f16(sacc[0][2 * jp + 1], qa[0][kk], kb[kk][2], kb[kk][3]);
                mma_f16(sacc[1][2 * jp + 1], qa[1][kk], kb[kk][2], kb[kk][3]);
            }
        }

        // ---- online softmax (log2 domain, half2 exp); P -> fp16 A-frags ----
        unsigned pa[2][4][4];
        #pragma unroll
        for (int mt = 0; mt < 2; ++mt) {
            float mx0 = -1e30f, mx1 = -1e30f;
            #pragma unroll
            for (int j = 0; j < 8; ++j) {
                mx0 = fmaxf(mx0, fmaxf(sacc[mt][j][0], sacc[mt][j][1]));
                mx1 = fmaxf(mx1, fmaxf(sacc[mt][j][2], sacc[mt][j][3]));
            }
            mx0 = fmaxf(mx0, __shfl_xor_sync(0xffffffffu, mx0, 1));
            mx0 = fmaxf(mx0, __shfl_xor_sync(0xffffffffu, mx0, 2));
            mx1 = fmaxf(mx1, __shfl_xor_sync(0xffffffffu, mx1, 1));
            mx1 = fmaxf(mx1, __shfl_xor_sync(0xffffffffu, mx1, 2));
            float mn0 = fmaxf(m[mt][0], mx0), mn1 = fmaxf(m[mt][1], mx1);
            float al0 = ex2f(m[mt][0] - mn0), al1 = ex2f(m[mt][1] - mn1);

            float rs0 = 0.f, rs1 = 0.f;
            #pragma unroll
            for (int j = 0; j < 8; ++j) {
                // two scores packed per MUFU op; result IS the PV fragment word
                unsigned u0 = h2ex2(cvth2(sacc[mt][j][1] - mn0, sacc[mt][j][0] - mn0));
                unsigned u1 = h2ex2(cvth2(sacc[mt][j][3] - mn1, sacc[mt][j][2] - mn1));
                pa[mt][j >> 1][(j & 1) * 2 + 0] = u0;
                pa[mt][j >> 1][(j & 1) * 2 + 1] = u1;
                float2 f0 = __half22float2(*reinterpret_cast<__half2*>(&u0));
                float2 f1 = __half22float2(*reinterpret_cast<__half2*>(&u1));
                rs0 += f0.x + f0.y;
                rs1 += f1.x + f1.y;
            }
            rs0 += __shfl_xor_sync(0xffffffffu, rs0, 1);
            rs0 += __shfl_xor_sync(0xffffffffu, rs0, 2);
            rs1 += __shfl_xor_sync(0xffffffffu, rs1, 1);
            rs1 += __shfl_xor_sync(0xffffffffu, rs1, 2);
            l[mt][0] = l[mt][0] * al0 + rs0;
            l[mt][1] = l[mt][1] * al1 + rs1;
            m[mt][0] = mn0; m[mt][1] = mn1;
            #pragma unroll
            for (int j = 0; j < 8; ++j) {
                oacc[mt][j][0] *= al0; oacc[mt][j][1] *= al0;
                oacc[mt][j][2] *= al1; oacc[mt][j][3] *= al1;
            }
        }

        // ---- O += P V (V via ldmatrix.trans) ----
        #pragma unroll
        for (int kk2 = 0; kk2 < 4; ++kk2) {
            unsigned vb[4][4];
            #pragma unroll
            for (int jp = 0; jp < 4; ++jp)
                ldm4t(vb[jp], Vb + swz(16 * kk2 + rV, 2 * jp + cV) * 16);
            #pragma unroll
            for (int jp = 0; jp < 4; ++jp) {
                mma_f16(oacc[0][2 * jp],     pa[0][kk2], vb[jp][0], vb[jp][1]);
                mma_f16(oacc[1][2 * jp],     pa[1][kk2], vb[jp][0], vb[jp][1]);
                mma_f16(oacc[0][2 * jp + 1], pa[0][kk2], vb[jp][2], vb[jp][3]);
                mma_f16(oacc[1][2 * jp + 1], pa[1][kk2], vb[jp][2], vb[jp][3]);
            }
        }
    }

    // epilogue: normalize, store fp16 to g_attn
    #pragma unroll
    for (int mt = 0; mt < 2; ++mt) {
        float inv0 = 1.0f / l[mt][0], inv1 = 1.0f / l[mt][1];
        int row0 = qblk * 128 + qr + 16 * mt + g;
        #pragma unroll
        for (int j = 0; j < 8; ++j) {
            int c0 = h * D_ + 8 * j + 2 * t;
            *reinterpret_cast<unsigned*>(g_attn + ((size_t)(b * S_ + row0)) * E_ + c0) =
                packh2(oacc[mt][j][0] * inv0, oacc[mt][j][1] * inv0);
            *reinterpret_cast<unsigned*>(g_attn + ((size_t)(b * S_ + row0 + 8)) * E_ + c0) =
                packh2(oacc[mt][j][2] * inv1, oacc[mt][j][3] * inv1);
        }
    }
}

// ---------------------------------------------------------------------------
// Output projection: C[8192,1024] = attn @ W^T + bias, fp16 mma.
// CTA 128x128, 4 warps (2x2) of 64x64 tiles, BK=64, double-buffered.
// ---------------------------------------------------------------------------
#define PTILE_B (128 * 128)

__global__ void __launch_bounds__(128, 2)
proj_kernel(const float* __restrict__ bias, float* __restrict__ C) {
    extern __shared__ __align__(16) unsigned char smraw[];
    const unsigned sb = stou(smraw);

    const int tid = threadIdx.x, wid = tid >> 5, lane = tid & 31;
    const int g = lane >> 2, t = lane & 3;
    const int wm = wid & 1, wn = wid >> 1;
    const int bm0 = blockIdx.y * 128, bn0 = blockIdx.x * 128;

    auto load_tile = [&](int kt, int buf) {
        unsigned ad = sb + buf * (2 * PTILE_B);
        unsigned bd = ad + PTILE_B;
        #pragma unroll
        for (int n = 0; n < 8; ++n) {
            int c = tid + 128 * n;
            int r = c >> 3, cb = c & 7;
            cp16(ad + swz(r, cb) * 16, g_attn + (size_t)(bm0 + r) * E_ + kt * 64 + cb * 8);
            cp16(bd + swz(r, cb) * 16, g_wh   + (size_t)(bn0 + r) * E_ + kt * 64 + cb * 8);
        }
    };

    float acc[4][8][4] = {};
    load_tile(0, 0); cp_commit();

    const int rA = lane & 15, cA = lane >> 4;
    const int rB = ((lane & 16) >> 1) + (lane & 7), cB = (lane >> 3) & 1;

    for (int kt = 0; kt < E_ / 64; ++kt) {
        if (kt + 1 < E_ / 64) { load_tile(kt + 1, (kt + 1) & 1); cp_commit(); cp_wait<1>(); }
        else                  { cp_wait<0>(); }
        __syncthreads();
        const unsigned As = sb + (kt & 1) * (2 * PTILE_B);
        const unsigned Bs = As + PTILE_B;

        unsigned a[4][4][4];
        #pragma unroll
        for (int mt = 0; mt < 4; ++mt)
            #pragma unroll
            for (int kk = 0; kk < 4; ++kk)
                ldm4(a[mt][kk], As + swz(64 * wm + 16 * mt + rA, 2 * kk + cA) * 16);

        #pragma unroll
        for (int jp = 0; jp < 4; ++jp) {
            unsigned wb[4][4];
            #pragma unroll
            for (int kk = 0; kk < 4; ++kk)
                ldm4(wb[kk], Bs + swz(64 * wn + 16 * jp + rB, 2 * kk + cB) * 16);
            #pragma unroll
            for (int kk = 0; kk < 4; ++kk)
                #pragma unroll
                for (int mt = 0; mt < 4; ++mt) {
                    mma_f16(acc[mt][2 * jp],     a[mt][kk], wb[kk][0], wb[kk][1]);
                    mma_f16(acc[mt][2 * jp + 1], a[mt][kk], wb[kk][2], wb[kk][3]);
                }
        }
        __syncthreads();
    }

    #pragma unroll
    for (int mt = 0; mt < 4; ++mt) {
        int row = bm0 + 64 * wm + 16 * mt + g;
        #pragma unroll
        for (int j = 0; j < 8; ++j) {
            int n0 = bn0 + 64 * wn + 8 * j + 2 * t;
            float bv0 = bias[n0], bv1 = bias[n0 + 1];
            *(float2*)(C + (size_t)row * E_ + n0) =
                make_float2(acc[mt][j][0] + bv0, acc[mt][j][1] + bv1);
            *(float2*)(C + (size_t)(row + 8) * E_ + n0) =
                make_float2(acc[mt][j][2] + bv0, acc[mt][j][3] + bv1);
        }
    }
}

extern "C" void kernel_launch(void* const* d_in, const int* in_sizes, int n_in,
                              void* d_out, int out_size) {
    const float* q    = (const float*)d_in[0];
    const float* k    = (const float*)d_in[1];
    const float* v    = (const float*)d_in[2];
    const float* w    = (const float*)d_in[3];
    const float* bias = (const float*)d_in[4];
    float* out = (float*)d_out;

    const int attn_smem = QTILE_B + NSTAGE * KVSTAGE_B;   // 81920
    const int proj_smem = 4 * PTILE_B;                    // 65536
    cudaFuncSetAttribute(attn_kernel, cudaFuncAttributeMaxDynamicSharedMemorySize, attn_smem);
    cudaFuncSetAttribute(proj_kernel, cudaFuncAttributeMaxDynamicSharedMemorySize, proj_smem);

    const int ntot = 3 * NQ4 + NW4;
    cvt_all_kernel<<<(ntot + 255) / 256, 256>>>(q, k, v, w);

    attn_kernel<<<dim3(S_ / 128, B_ * H_), 128, attn_smem>>>();
    proj_kernel<<<dim3(E_ / 128, (B_ * S_) / 128), 128, proj_smem>>>(bias, out);
}